// round 10
// baseline (speedup 1.0000x reference)
#include <cuda_runtime.h>
#include <cuda_bf16.h>
#include <cstdint>
#include <math.h>

// Problem constants
#define BB 2
#define TT 2048
#define DD 1024
#define HH 16
#define HD 64
#define MM (BB*TT)   // 4096

// Scratch (device globals: allocation-free)
__device__ __nv_bfloat16 g_qhi[BB*HH*TT*HD];
__device__ __nv_bfloat16 g_qlo[BB*HH*TT*HD];
__device__ __nv_bfloat16 g_khi[BB*HH*TT*HD];
__device__ __nv_bfloat16 g_klo[BB*HH*TT*HD];
__device__ __nv_bfloat16 g_vhi[BB*HH*TT*HD];
__device__ __nv_bfloat16 g_vlo[BB*HH*TT*HD];
__device__ float g_attn[BB*TT*DD];    // [B,T,D] attention output (rna-rounded)

// tf32(rna)-rounded copies of GEMM operands
__device__ float g_qc[MM*DD];
__device__ float g_kc[MM*DD];
__device__ float g_vc[MM*DD];
__device__ float g_Wqc[DD*DD];
__device__ float g_Wkc[DD*DD];
__device__ float g_Wvc[DD*DD];
__device__ float g_Woc[DD*DD];

// ===========================================================================
// Helpers
// ===========================================================================
__device__ __forceinline__ uint32_t smem_u32(const void* p) {
    uint32_t a;
    asm("{ .reg .u64 t; cvta.to.shared.u64 t, %1; cvt.u32.u64 %0, t; }"
        : "=r"(a) : "l"(p));
    return a;
}

__device__ __forceinline__ void cp_async16(uint32_t dst, const void* src) {
    asm volatile("cp.async.cg.shared.global [%0], [%1], 16;\n"
                 :: "r"(dst), "l"(src));
}

__device__ __forceinline__ uint32_t f2tf32(float x) {
    uint32_t r;
    asm("cvt.rna.tf32.f32 %0, %1;" : "=r"(r) : "f"(x));
    return r;
}

__device__ __forceinline__ void mma_tf32(float* c, const uint32_t* a,
                                         const uint32_t* b) {
    asm volatile(
        "mma.sync.aligned.m16n8k8.row.col.f32.tf32.tf32.f32 "
        "{%0,%1,%2,%3}, {%4,%5,%6,%7}, {%8,%9}, {%0,%1,%2,%3};\n"
        : "+f"(c[0]), "+f"(c[1]), "+f"(c[2]), "+f"(c[3])
        : "r"(a[0]), "r"(a[1]), "r"(a[2]), "r"(a[3]),
          "r"(b[0]), "r"(b[1]));
}

__device__ __forceinline__ void mma_bf16(float* c, const uint32_t* a,
                                         const uint32_t* b) {
    asm volatile(
        "mma.sync.aligned.m16n8k16.row.col.f32.bf16.bf16.f32 "
        "{%0,%1,%2,%3}, {%4,%5,%6,%7}, {%8,%9}, {%0,%1,%2,%3};\n"
        : "+f"(c[0]), "+f"(c[1]), "+f"(c[2]), "+f"(c[3])
        : "r"(a[0]), "r"(a[1]), "r"(a[2]), "r"(a[3]),
          "r"(b[0]), "r"(b[1]));
}

__device__ __forceinline__ void ldsm4(uint32_t* r, uint32_t addr) {
    asm volatile(
        "ldmatrix.sync.aligned.m8n8.x4.shared.b16 {%0,%1,%2,%3}, [%4];"
        : "=r"(r[0]), "=r"(r[1]), "=r"(r[2]), "=r"(r[3]) : "r"(addr));
}

__device__ __forceinline__ void ldsm4t(uint32_t* r, uint32_t addr) {
    asm volatile(
        "ldmatrix.sync.aligned.m8n8.x4.trans.shared.b16 {%0,%1,%2,%3}, [%4];"
        : "=r"(r[0]), "=r"(r[1]), "=r"(r[2]), "=r"(r[3]) : "r"(addr));
}

// Split (x,y) into hi/lo bf16x2 words (low half = x).
__device__ __forceinline__ void split2(float x, float y,
                                       uint32_t& hi, uint32_t& lo) {
    __nv_bfloat16 hx = __float2bfloat16(x);
    __nv_bfloat16 hy = __float2bfloat16(y);
    __nv_bfloat16 lx = __float2bfloat16(x - __bfloat162float(hx));
    __nv_bfloat16 ly = __float2bfloat16(y - __bfloat162float(hy));
    __nv_bfloat162 ph = __halves2bfloat162(hx, hy);
    __nv_bfloat162 pl = __halves2bfloat162(lx, ly);
    hi = *(uint32_t*)&ph;
    lo = *(uint32_t*)&pl;
}

// ===========================================================================
// Pre-pass: rna-round all 7 operand arrays in ONE launch.
// ===========================================================================
__global__ void __launch_bounds__(256) cvt_all_kernel(
    const float* __restrict__ q, const float* __restrict__ k,
    const float* __restrict__ v,
    const float* __restrict__ Wq, const float* __restrict__ Wk,
    const float* __restrict__ Wv, const float* __restrict__ Wo)
{
    int z = blockIdx.y;
    const float* src;
    float* dst;
    int n;
    switch (z) {
        case 0: src = q;  dst = g_qc;  n = MM * DD; break;
        case 1: src = k;  dst = g_kc;  n = MM * DD; break;
        case 2: src = v;  dst = g_vc;  n = MM * DD; break;
        case 3: src = Wq; dst = g_Wqc; n = DD * DD; break;
        case 4: src = Wk; dst = g_Wkc; n = DD * DD; break;
        case 5: src = Wv; dst = g_Wvc; n = DD * DD; break;
        default: src = Wo; dst = g_Woc; n = DD * DD; break;
    }
    int i = (blockIdx.x * 256 + threadIdx.x) * 4;
    if (i < n) {
        float4 val = *(const float4*)(src + i);
        val.x = __uint_as_float(f2tf32(val.x));
        val.y = __uint_as_float(f2tf32(val.y));
        val.z = __uint_as_float(f2tf32(val.z));
        val.w = __uint_as_float(f2tf32(val.w));
        *(float4*)(dst + i) = val;
    }
}

// ===========================================================================
// tf32 mma.sync GEMM mainloop: ST=20 padded smem (proven conflict-free),
// 3-stage cp.async pipeline (60KB) -> 3 CTAs/SM. ldmatrix fragments.
// Operands pre-rounded to tf32 (rna).
// ===========================================================================
#define KC 16
#define ST 20
#define GST (128 * ST)            // floats per stage per operand
#define GSTAGES 3
#define GEMM_SMEM (2 * GSTAGES * GST * 4)   // 61440 bytes

struct GemmFrag { float acc[2][8][4]; int m0base, n0base; };

__device__ __forceinline__ void gemm_mainloop(
    const float* __restrict__ A, const float* __restrict__ W,
    float* smemf, GemmFrag& F)
{
    float* As = smemf;
    float* Bs = smemf + GSTAGES * GST;

    const int tid = threadIdx.x;
    const int wid = tid >> 5;
    const int lane = tid & 31;
    const int g = lane >> 2;
    const int t = lane & 3;
    const int bm = blockIdx.y * 128;
    const int bn = blockIdx.x * 128;
    const int wm = (wid & 3) * 32;
    const int wn = (wid >> 2) * 64;

    const uint32_t aB = smem_u32(As);
    const uint32_t bB = smem_u32(Bs);
    const int lrow = tid >> 2;
    const int lseg = tid & 3;

    const uint32_t a_base0 = aB + (uint32_t)((wm + (lane & 15)) * ST
                           + ((lane >> 4) << 2)) * 4;
    const uint32_t a_base1 = a_base0 + 16 * ST * 4;
    uint32_t b_base[4];
#pragma unroll
    for (int i = 0; i < 4; i++)
        b_base[i] = bB + (uint32_t)((wn + 16 * i + ((lane >> 4) << 3)
                   + (lane & 7)) * ST + (((lane >> 3) & 1) << 2)) * 4;

#pragma unroll
    for (int mt = 0; mt < 2; mt++)
#pragma unroll
        for (int nt = 0; nt < 8; nt++)
#pragma unroll
            for (int i = 0; i < 4; i++) F.acc[mt][nt][i] = 0.f;

    const int NC = DD / KC;   // 64

    auto issue = [&](int c) {
        int s = c % GSTAGES;
#pragma unroll
        for (int i = 0; i < 2; i++) {
            int row = lrow + i * 64;
            uint32_t soff = (uint32_t)(s * GST + row * ST + lseg * 4) * 4;
            const float* ag = A + (size_t)(bm + row) * DD + c * KC + lseg * 4;
            const float* wg = W + (size_t)(bn + row) * DD + c * KC + lseg * 4;
            cp_async16(aB + soff, ag);
            cp_async16(bB + soff, wg);
        }
        asm volatile("cp.async.commit_group;\n" ::: "memory");
    };

    issue(0); issue(1);

    for (int c = 0; c < NC; c++) {
        if (c < NC - 1) asm volatile("cp.async.wait_group 1;\n" ::: "memory");
        else            asm volatile("cp.async.wait_group 0;\n" ::: "memory");
        __syncthreads();   // chunk c visible; prev iteration's reads done

        if (c + 2 < NC) issue(c + 2);

        const uint32_t soff = (uint32_t)((c % GSTAGES) * GST) * 4;
#pragma unroll
        for (int ks = 0; ks < 2; ks++) {
            const uint32_t koff = soff + ks * 32;   // +8 floats
            uint32_t af0[4], af1[4];
            ldsm4(af0, a_base0 + koff);
            ldsm4(af1, a_base1 + koff);
#pragma unroll
            for (int i = 0; i < 4; i++) {
                uint32_t bb[4];
                ldsm4(bb, b_base[i] + koff);
                mma_tf32(F.acc[0][2 * i],     af0, &bb[0]);
                mma_tf32(F.acc[0][2 * i + 1], af0, &bb[2]);
                mma_tf32(F.acc[1][2 * i],     af1, &bb[0]);
                mma_tf32(F.acc[1][2 * i + 1], af1, &bb[2]);
            }
        }
        __syncthreads();
    }
    F.m0base = bm + wm + g;
    F.n0base = bn + wn + 2 * t;
}

// Fused Q/K/V projections, epilogue splits to bf16 hi/lo head tensors.
__global__ void __launch_bounds__(256, 3) gemm_qkv_kernel(
    const float* __restrict__ bq, const float* __restrict__ bk,
    const float* __restrict__ bv)
{
    extern __shared__ float smemf[];
    int z = blockIdx.z;
    const float* A = (z == 0) ? g_qc : (z == 1) ? g_kc : g_vc;
    const float* W = (z == 0) ? g_Wqc : (z == 1) ? g_Wkc : g_Wvc;
    const float* bias = (z == 0) ? bq : (z == 1) ? bk : bv;
    __nv_bfloat16* Hi = (z == 0) ? g_qhi : (z == 1) ? g_khi : g_vhi;
    __nv_bfloat16* Lo = (z == 0) ? g_qlo : (z == 1) ? g_klo : g_vlo;
    const float scale = (z == 0) ? 0.125f : 1.0f;

    GemmFrag F;
    gemm_mainloop(A, W, smemf, F);

#pragma unroll
    for (int mt = 0; mt < 2; mt++) {
#pragma unroll
        for (int nt = 0; nt < 8; nt++) {
            int m0 = F.m0base + mt * 16;
            int n0 = F.n0base + nt * 8;
            float b0 = bias[n0], b1 = bias[n0 + 1];
            int h = n0 >> 6, d = n0 & 63;
            int b = m0 >> 11, t0 = m0 & 2047;
            size_t idx0 = (((size_t)b * HH + h) * TT + t0) * HD + d;
            uint32_t hi, lo;
            split2((F.acc[mt][nt][0] + b0) * scale,
                   (F.acc[mt][nt][1] + b1) * scale, hi, lo);
            *(uint32_t*)&Hi[idx0] = hi;
            *(uint32_t*)&Lo[idx0] = lo;
            split2((F.acc[mt][nt][2] + b0) * scale,
                   (F.acc[mt][nt][3] + b1) * scale, hi, lo);
            *(uint32_t*)&Hi[idx0 + 8 * HD] = hi;
            *(uint32_t*)&Lo[idx0 + 8 * HD] = lo;
        }
    }
}

// O projection: fp32 epilogue to d_out.
__global__ void __launch_bounds__(256, 3) gemm_o_kernel(
    const float* __restrict__ bias, float* __restrict__ C)
{
    extern __shared__ float smemf[];
    GemmFrag F;
    gemm_mainloop(g_attn, g_Woc, smemf, F);

#pragma unroll
    for (int mt = 0; mt < 2; mt++) {
#pragma unroll
        for (int nt = 0; nt < 8; nt++) {
            int m0 = F.m0base + mt * 16;
            int n0 = F.n0base + nt * 8;
            float b0 = bias[n0], b1 = bias[n0 + 1];
            float2 r0 = make_float2(F.acc[mt][nt][0] + b0,
                                    F.acc[mt][nt][1] + b1);
            float2 r1 = make_float2(F.acc[mt][nt][2] + b0,
                                    F.acc[mt][nt][3] + b1);
            *(float2*)(C + (size_t)m0 * DD + n0) = r0;
            *(float2*)(C + (size_t)(m0 + 8) * DD + n0) = r1;
        }
    }
}

// ===========================================================================
// Flash attention (round-8 proven): pre-split bf16 inputs, double-buffered
// cp.async KV, ldmatrix frags, split-bf16 mma, fixed-shift softmax.
// ===========================================================================
#define QLB 18432
#define KVB 36864
#define KVBUF 36864
#define FLASH_SMEM 110592
#define FSHIFT 8.0f

__global__ void __launch_bounds__(256, 2) flash_tc_kernel(float* __restrict__ Out)
{
    extern __shared__ uint32_t sm[];
    const uint32_t sb = smem_u32(sm);

    const int tid = threadIdx.x;
    const int wid = tid >> 5;
    const int lane = tid & 31;
    const int g = lane >> 2;
    const int t = lane & 3;
    const int qt = blockIdx.x;
    const int h  = blockIdx.y;
    const int b  = blockIdx.z;

    const size_t bh = ((size_t)b * HH + h) * TT * HD;
    const __nv_bfloat16* Qhi = g_qhi + bh + (size_t)qt * 128 * HD;
    const __nv_bfloat16* Qlo = g_qlo + bh + (size_t)qt * 128 * HD;
    const __nv_bfloat16* Khi = g_khi + bh;
    const __nv_bfloat16* Klo = g_klo + bh;
    const __nv_bfloat16* Vhi = g_vhi + bh;
    const __nv_bfloat16* Vlo = g_vlo + bh;

#pragma unroll
    for (int it = 0; it < 8; it++) {
        int lin = tid + it * 256;
        int arr = it >> 2;
        int rem = lin & 1023;
        int row = rem >> 3;
        int seg = rem & 7;
        const __nv_bfloat16* src = (arr == 0 ? Qhi : Qlo) + row * HD + seg * 8;
        cp_async16(sb + arr * QLB + row * 144 + seg * 16, src);
    }

    auto issue_kv = [&](int jt, int s) {
#pragma unroll
        for (int it = 0; it < 8; it++) {
            int lin = tid + it * 256;
            int arr = it >> 1;
            int rem = lin & 511;
            int row = rem >> 3;
            int seg = rem & 7;
            const __nv_bfloat16* base =
                (arr == 0) ? Khi : (arr == 1) ? Klo : (arr == 2) ? Vhi : Vlo;
            cp_async16(sb + KVB + s * KVBUF + arr * 9216 + row * 144 + seg * 16,
                       base + (size_t)(jt * 64 + row) * HD + seg * 8);
        }
        asm volatile("cp.async.commit_group;\n" ::: "memory");
    };

    issue_kv(0, 0);

    float o[8][4];
#pragma unroll
    for (int j = 0; j < 8; j++)
#pragma unroll
        for (int i = 0; i < 4; i++) o[j][i] = 0.f;
    float li0 = 0.f, li1 = 0.f;

    const int mq = wid * 16;
    const uint32_t qa_base = sb + (mq + (lane & 15)) * 144 + ((lane >> 4) << 4);
    const uint32_t ka_off = (((lane >> 4) << 3) + (lane & 7)) * 144
                          + (((lane >> 3) & 1) << 4);
    const uint32_t va_off = ((((lane >> 3) & 1) << 3) + (lane & 7)) * 144
                          + ((lane >> 4) << 4);

    for (int jt = 0; jt < TT / 64; jt++) {
        asm volatile("cp.async.wait_group 0;\n" ::: "memory");
        __syncthreads();

        if (jt + 1 < TT / 64) issue_kv(jt + 1, (jt + 1) & 1);

        const uint32_t kbuf = sb + KVB + (jt & 1) * KVBUF;

        float sc[8][4];
#pragma unroll
        for (int j = 0; j < 8; j++)
#pragma unroll
            for (int i = 0; i < 4; i++) sc[j][i] = 0.f;

#pragma unroll
        for (int kb = 0; kb < 4; kb++) {
            uint32_t aH[4], aL[4];
            ldsm4(aH, qa_base + kb * 32);
            ldsm4(aL, qa_base + kb * 32 + QLB);
#pragma unroll
            for (int jp = 0; jp < 4; jp++) {
                uint32_t kaddr = kbuf + ka_off + jp * 16 * 144 + kb * 32;
                uint32_t bH[4], bL[4];
                ldsm4(bH, kaddr);
                ldsm4(bL, kaddr + 9216);
                mma_bf16(sc[2 * jp],     aH, &bH[0]);
                mma_bf16(sc[2 * jp],     aH, &bL[0]);
                mma_bf16(sc[2 * jp],     aL, &bH[0]);
                mma_bf16(sc[2 * jp + 1], aH, &bH[2]);
                mma_bf16(sc[2 * jp + 1], aH, &bL[2]);
                mma_bf16(sc[2 * jp + 1], aL, &bH[2]);
            }
        }

        float rs0 = 0.f, rs1 = 0.f;
#pragma unroll
        for (int j = 0; j < 8; j++) {
            sc[j][0] = __expf(sc[j][0] - FSHIFT);
            sc[j][1] = __expf(sc[j][1] - FSHIFT);
            sc[j][2] = __expf(sc[j][2] - FSHIFT);
            sc[j][3] = __expf(sc[j][3] - FSHIFT);
            rs0 += sc[j][0] + sc[j][1];
            rs1 += sc[j][2] + sc[j][3];
        }
        li0 += rs0;
        li1 += rs1;

#pragma unroll
        for (int kb = 0; kb < 4; kb++) {
            uint32_t aH[4], aL[4];
            split2(sc[2 * kb][0],     sc[2 * kb][1],     aH[0], aL[0]);
            split2(sc[2 * kb][2],     sc[2 * kb][3],     aH[1], aL[1]);
            split2(sc[2 * kb + 1][0], sc[2 * kb + 1][1], aH[2], aL[2]);
            split2(sc[2 * kb + 1][2], sc[2 * kb + 1][3], aH[3], aL[3]);
#pragma unroll
            for (int jp = 0; jp < 4; jp++) {
                uint32_t vaddr = kbuf + 18432 + va_off + kb * 16 * 144 + jp * 32;
                uint32_t bH[4], bL[4];
                ldsm4t(bH, vaddr);
                ldsm4t(bL, vaddr + 9216);
                mma_bf16(o[2 * jp],     aH, &bH[0]);
                mma_bf16(o[2 * jp],     aH, &bL[0]);
                mma_bf16(o[2 * jp],     aL, &bH[0]);
                mma_bf16(o[2 * jp + 1], aH, &bH[2]);
                mma_bf16(o[2 * jp + 1], aH, &bL[2]);
                mma_bf16(o[2 * jp + 1], aL, &bH[2]);
            }
        }
    }

    li0 += __shfl_xor_sync(0xffffffffu, li0, 1);
    li0 += __shfl_xor_sync(0xffffffffu, li0, 2);
    li1 += __shfl_xor_sync(0xffffffffu, li1, 1);
    li1 += __shfl_xor_sync(0xffffffffu, li1, 2);
    float inv0 = 1.f / li0, inv1 = 1.f / li1;
    int row0 = qt * 128 + mq + g;
#pragma unroll
    for (int j = 0; j < 8; j++) {
        int col = h * HD + j * 8 + 2 * t;
        float2 r0 = make_float2(__uint_as_float(f2tf32(o[j][0] * inv0)),
                                __uint_as_float(f2tf32(o[j][1] * inv0)));
        float2 r1 = make_float2(__uint_as_float(f2tf32(o[j][2] * inv1)),
                                __uint_as_float(f2tf32(o[j][3] * inv1)));
        *(float2*)(Out + ((size_t)b * TT + row0) * DD + col) = r0;
        *(float2*)(Out + ((size_t)b * TT + row0 + 8) * DD + col) = r1;
    }
}

// ---------------------------------------------------------------------------
extern "C" void kernel_launch(void* const* d_in, const int* in_sizes, int n_in,
                              void* d_out, int out_size)
{
    const float* q  = (const float*)d_in[0];
    const float* k  = (const float*)d_in[1];
    const float* v  = (const float*)d_in[2];
    const float* Wq = (const float*)d_in[3];
    const float* bq = (const float*)d_in[4];
    const float* Wk = (const float*)d_in[5];
    const float* bk = (const float*)d_in[6];
    const float* Wv = (const float*)d_in[7];
    const float* bv = (const float*)d_in[8];
    const float* Wo = (const float*)d_in[9];
    const float* bo = (const float*)d_in[10];
    float* out = (float*)d_out;

    float* attn;
    cudaGetSymbolAddress((void**)&attn, g_attn);

    cudaFuncSetAttribute(flash_tc_kernel,
                         cudaFuncAttributeMaxDynamicSharedMemorySize, FLASH_SMEM);
    cudaFuncSetAttribute(gemm_qkv_kernel,
                         cudaFuncAttributeMaxDynamicSharedMemorySize, GEMM_SMEM);
    cudaFuncSetAttribute(gemm_o_kernel,
                         cudaFuncAttributeMaxDynamicSharedMemorySize, GEMM_SMEM);

    dim3 cgrid((MM * DD) / (256 * 4), 7);
    cvt_all_kernel<<<cgrid, 256>>>(q, k, v, Wq, Wk, Wv, Wo);

    dim3 qkvgrid(DD / 128, MM / 128, 3);   // (8, 32, 3)
    gemm_qkv_kernel<<<qkvgrid, 256, GEMM_SMEM>>>(bq, bk, bv);

    dim3 fgrid(TT / 128, HH, BB);          // (16, 16, 2)
    flash_tc_kernel<<<fgrid, 256, FLASH_SMEM>>>(attn);

    dim3 ogrid(DD / 128, MM / 128);        // (8, 32)
    gemm_o_kernel<<<ogrid, 256, GEMM_SMEM>>>(bo, out);
}

// round 11
// speedup vs baseline: 1.2953x; 1.2953x over previous
#include <cuda_runtime.h>
#include <cuda_bf16.h>
#include <cstdint>
#include <math.h>

// Problem constants
#define BB 2
#define TT 2048
#define DD 1024
#define HH 16
#define HD 64
#define MM (BB*TT)   // 4096

// Scratch (device globals: allocation-free)
__device__ __nv_bfloat16 g_qhi[BB*HH*TT*HD];
__device__ __nv_bfloat16 g_qlo[BB*HH*TT*HD];
__device__ __nv_bfloat16 g_khi[BB*HH*TT*HD];
__device__ __nv_bfloat16 g_klo[BB*HH*TT*HD];
__device__ __nv_bfloat16 g_vhi[BB*HH*TT*HD];
__device__ __nv_bfloat16 g_vlo[BB*HH*TT*HD];
__device__ float g_attn[BB*TT*DD];    // [B,T,D] attention output (rna-rounded)

// tf32(rna)-rounded copies of GEMM operands
__device__ float g_qc[MM*DD];
__device__ float g_kc[MM*DD];
__device__ float g_vc[MM*DD];
__device__ float g_Wqc[DD*DD];
__device__ float g_Wkc[DD*DD];
__device__ float g_Wvc[DD*DD];
__device__ float g_Woc[DD*DD];

// ===========================================================================
// Helpers
// ===========================================================================
__device__ __forceinline__ uint32_t smem_u32(const void* p) {
    uint32_t a;
    asm("{ .reg .u64 t; cvta.to.shared.u64 t, %1; cvt.u32.u64 %0, t; }"
        : "=r"(a) : "l"(p));
    return a;
}

__device__ __forceinline__ void cp_async16(uint32_t dst, const void* src) {
    asm volatile("cp.async.cg.shared.global [%0], [%1], 16;\n"
                 :: "r"(dst), "l"(src));
}

__device__ __forceinline__ uint32_t f2tf32(float x) {
    uint32_t r;
    asm("cvt.rna.tf32.f32 %0, %1;" : "=r"(r) : "f"(x));
    return r;
}

__device__ __forceinline__ void mma_tf32(float* c, const uint32_t* a,
                                         const uint32_t* b) {
    asm volatile(
        "mma.sync.aligned.m16n8k8.row.col.f32.tf32.tf32.f32 "
        "{%0,%1,%2,%3}, {%4,%5,%6,%7}, {%8,%9}, {%0,%1,%2,%3};\n"
        : "+f"(c[0]), "+f"(c[1]), "+f"(c[2]), "+f"(c[3])
        : "r"(a[0]), "r"(a[1]), "r"(a[2]), "r"(a[3]),
          "r"(b[0]), "r"(b[1]));
}

__device__ __forceinline__ void mma_bf16(float* c, const uint32_t* a,
                                         const uint32_t* b) {
    asm volatile(
        "mma.sync.aligned.m16n8k16.row.col.f32.bf16.bf16.f32 "
        "{%0,%1,%2,%3}, {%4,%5,%6,%7}, {%8,%9}, {%0,%1,%2,%3};\n"
        : "+f"(c[0]), "+f"(c[1]), "+f"(c[2]), "+f"(c[3])
        : "r"(a[0]), "r"(a[1]), "r"(a[2]), "r"(a[3]),
          "r"(b[0]), "r"(b[1]));
}

__device__ __forceinline__ void ldsm4(uint32_t* r, uint32_t addr) {
    asm volatile(
        "ldmatrix.sync.aligned.m8n8.x4.shared.b16 {%0,%1,%2,%3}, [%4];"
        : "=r"(r[0]), "=r"(r[1]), "=r"(r[2]), "=r"(r[3]) : "r"(addr));
}

__device__ __forceinline__ void ldsm4t(uint32_t* r, uint32_t addr) {
    asm volatile(
        "ldmatrix.sync.aligned.m8n8.x4.trans.shared.b16 {%0,%1,%2,%3}, [%4];"
        : "=r"(r[0]), "=r"(r[1]), "=r"(r[2]), "=r"(r[3]) : "r"(addr));
}

// Split (x,y) into hi/lo bf16x2 words (low half = x).
__device__ __forceinline__ void split2(float x, float y,
                                       uint32_t& hi, uint32_t& lo) {
    __nv_bfloat16 hx = __float2bfloat16(x);
    __nv_bfloat16 hy = __float2bfloat16(y);
    __nv_bfloat16 lx = __float2bfloat16(x - __bfloat162float(hx));
    __nv_bfloat16 ly = __float2bfloat16(y - __bfloat162float(hy));
    __nv_bfloat162 ph = __halves2bfloat162(hx, hy);
    __nv_bfloat162 pl = __halves2bfloat162(lx, ly);
    hi = *(uint32_t*)&ph;
    lo = *(uint32_t*)&pl;
}

// ===========================================================================
// Pre-pass: rna-round all 7 operand arrays in ONE launch.
// ===========================================================================
__global__ void __launch_bounds__(256) cvt_all_kernel(
    const float* __restrict__ q, const float* __restrict__ k,
    const float* __restrict__ v,
    const float* __restrict__ Wq, const float* __restrict__ Wk,
    const float* __restrict__ Wv, const float* __restrict__ Wo)
{
    int z = blockIdx.y;
    const float* src;
    float* dst;
    int n;
    switch (z) {
        case 0: src = q;  dst = g_qc;  n = MM * DD; break;
        case 1: src = k;  dst = g_kc;  n = MM * DD; break;
        case 2: src = v;  dst = g_vc;  n = MM * DD; break;
        case 3: src = Wq; dst = g_Wqc; n = DD * DD; break;
        case 4: src = Wk; dst = g_Wkc; n = DD * DD; break;
        case 5: src = Wv; dst = g_Wvc; n = DD * DD; break;
        default: src = Wo; dst = g_Woc; n = DD * DD; break;
    }
    int i = (blockIdx.x * 256 + threadIdx.x) * 4;
    if (i < n) {
        float4 val = *(const float4*)(src + i);
        val.x = __uint_as_float(f2tf32(val.x));
        val.y = __uint_as_float(f2tf32(val.y));
        val.z = __uint_as_float(f2tf32(val.z));
        val.w = __uint_as_float(f2tf32(val.w));
        *(float4*)(dst + i) = val;
    }
}

// ===========================================================================
// tf32 mma.sync GEMM mainloop: ST=20 padded smem (proven conflict-free),
// 4-stage cp.async pipeline (80KB, round-8 proven), ldmatrix fragments
// prefetched whole-chunk into registers, single barrier per chunk.
// Operands pre-rounded to tf32 (rna).
// ===========================================================================
#define KC 16
#define ST 20
#define GST (128 * ST)            // floats per stage per operand
#define GSTAGES 4
#define GEMM_SMEM (2 * GSTAGES * GST * 4)   // 81920 bytes

struct GemmFrag { float acc[2][8][4]; int m0base, n0base; };

__device__ __forceinline__ void gemm_mainloop(
    const float* __restrict__ A, const float* __restrict__ W,
    float* smemf, GemmFrag& F)
{
    float* As = smemf;
    float* Bs = smemf + GSTAGES * GST;

    const int tid = threadIdx.x;
    const int wid = tid >> 5;
    const int lane = tid & 31;
    const int g = lane >> 2;
    const int t = lane & 3;
    const int bm = blockIdx.y * 128;
    const int bn = blockIdx.x * 128;
    const int wm = (wid & 3) * 32;
    const int wn = (wid >> 2) * 64;

    const uint32_t aB = smem_u32(As);
    const uint32_t bB = smem_u32(Bs);
    const int lrow = tid >> 2;
    const int lseg = tid & 3;

    const uint32_t a_base0 = aB + (uint32_t)((wm + (lane & 15)) * ST
                           + ((lane >> 4) << 2)) * 4;
    const uint32_t a_base1 = a_base0 + 16 * ST * 4;
    uint32_t b_base[4];
#pragma unroll
    for (int i = 0; i < 4; i++)
        b_base[i] = bB + (uint32_t)((wn + 16 * i + ((lane >> 4) << 3)
                   + (lane & 7)) * ST + (((lane >> 3) & 1) << 2)) * 4;

#pragma unroll
    for (int mt = 0; mt < 2; mt++)
#pragma unroll
        for (int nt = 0; nt < 8; nt++)
#pragma unroll
            for (int i = 0; i < 4; i++) F.acc[mt][nt][i] = 0.f;

    const int NC = DD / KC;   // 64

    auto issue = [&](int c) {
        int s = c & (GSTAGES - 1);
#pragma unroll
        for (int i = 0; i < 2; i++) {
            int row = lrow + i * 64;
            uint32_t soff = (uint32_t)(s * GST + row * ST + lseg * 4) * 4;
            const float* ag = A + (size_t)(bm + row) * DD + c * KC + lseg * 4;
            const float* wg = W + (size_t)(bn + row) * DD + c * KC + lseg * 4;
            cp_async16(aB + soff, ag);
            cp_async16(bB + soff, wg);
        }
        asm volatile("cp.async.commit_group;\n" ::: "memory");
    };

    issue(0); issue(1); issue(2);

    for (int c = 0; c < NC; c++) {
        if (c < NC - 2)       asm volatile("cp.async.wait_group 2;\n" ::: "memory");
        else if (c == NC - 2) asm volatile("cp.async.wait_group 1;\n" ::: "memory");
        else                  asm volatile("cp.async.wait_group 0;\n" ::: "memory");
        __syncthreads();
        // NOTE: single barrier per chunk. This barrier proves every warp
        // finished iteration c-1's fragment reads, so issue(c+3) (which
        // overwrites stage (c-1)&3) is safe, and no tail barrier is needed.

        if (c + 3 < NC) issue(c + 3);

        const uint32_t soff = (uint32_t)((c & (GSTAGES - 1)) * GST) * 4;

        // Prefetch the ENTIRE chunk's fragments before the mma burst.
        uint32_t af0[2][4], af1[2][4], bb[2][4][4];
#pragma unroll
        for (int ks = 0; ks < 2; ks++) {
            const uint32_t koff = soff + ks * 32;
            ldsm4(af0[ks], a_base0 + koff);
            ldsm4(af1[ks], a_base1 + koff);
#pragma unroll
            for (int i = 0; i < 4; i++)
                ldsm4(bb[ks][i], b_base[i] + koff);
        }
#pragma unroll
        for (int ks = 0; ks < 2; ks++) {
#pragma unroll
            for (int i = 0; i < 4; i++) {
                mma_tf32(F.acc[0][2 * i],     af0[ks], &bb[ks][i][0]);
                mma_tf32(F.acc[0][2 * i + 1], af0[ks], &bb[ks][i][2]);
                mma_tf32(F.acc[1][2 * i],     af1[ks], &bb[ks][i][0]);
                mma_tf32(F.acc[1][2 * i + 1], af1[ks], &bb[ks][i][2]);
            }
        }
    }
    __syncthreads();   // protect smem reuse by any epilogue usage
    F.m0base = bm + wm + g;
    F.n0base = bn + wn + 2 * t;
}

// Fused Q/K/V projections, epilogue splits to bf16 hi/lo head tensors.
__global__ void __launch_bounds__(256, 2) gemm_qkv_kernel(
    const float* __restrict__ bq, const float* __restrict__ bk,
    const float* __restrict__ bv)
{
    extern __shared__ float smemf[];
    int z = blockIdx.z;
    const float* A = (z == 0) ? g_qc : (z == 1) ? g_kc : g_vc;
    const float* W = (z == 0) ? g_Wqc : (z == 1) ? g_Wkc : g_Wvc;
    const float* bias = (z == 0) ? bq : (z == 1) ? bk : bv;
    __nv_bfloat16* Hi = (z == 0) ? g_qhi : (z == 1) ? g_khi : g_vhi;
    __nv_bfloat16* Lo = (z == 0) ? g_qlo : (z == 1) ? g_klo : g_vlo;
    const float scale = (z == 0) ? 0.125f : 1.0f;

    GemmFrag F;
    gemm_mainloop(A, W, smemf, F);

#pragma unroll
    for (int mt = 0; mt < 2; mt++) {
#pragma unroll
        for (int nt = 0; nt < 8; nt++) {
            int m0 = F.m0base + mt * 16;
            int n0 = F.n0base + nt * 8;
            float b0 = bias[n0], b1 = bias[n0 + 1];
            int h = n0 >> 6, d = n0 & 63;
            int b = m0 >> 11, t0 = m0 & 2047;
            size_t idx0 = (((size_t)b * HH + h) * TT + t0) * HD + d;
            uint32_t hi, lo;
            split2((F.acc[mt][nt][0] + b0) * scale,
                   (F.acc[mt][nt][1] + b1) * scale, hi, lo);
            *(uint32_t*)&Hi[idx0] = hi;
            *(uint32_t*)&Lo[idx0] = lo;
            split2((F.acc[mt][nt][2] + b0) * scale,
                   (F.acc[mt][nt][3] + b1) * scale, hi, lo);
            *(uint32_t*)&Hi[idx0 + 8 * HD] = hi;
            *(uint32_t*)&Lo[idx0 + 8 * HD] = lo;
        }
    }
}

// O projection: fp32 epilogue to d_out.
__global__ void __launch_bounds__(256, 2) gemm_o_kernel(
    const float* __restrict__ bias, float* __restrict__ C)
{
    extern __shared__ float smemf[];
    GemmFrag F;
    gemm_mainloop(g_attn, g_Woc, smemf, F);

#pragma unroll
    for (int mt = 0; mt < 2; mt++) {
#pragma unroll
        for (int nt = 0; nt < 8; nt++) {
            int m0 = F.m0base + mt * 16;
            int n0 = F.n0base + nt * 8;
            float b0 = bias[n0], b1 = bias[n0 + 1];
            float2 r0 = make_float2(F.acc[mt][nt][0] + b0,
                                    F.acc[mt][nt][1] + b1);
            float2 r1 = make_float2(F.acc[mt][nt][2] + b0,
                                    F.acc[mt][nt][3] + b1);
            *(float2*)(C + (size_t)m0 * DD + n0) = r0;
            *(float2*)(C + (size_t)(m0 + 8) * DD + n0) = r1;
        }
    }
}

// ===========================================================================
// Flash attention (round-8 proven, unchanged): pre-split bf16 inputs,
// double-buffered cp.async KV, ldmatrix frags, split-bf16 mma,
// fixed-shift softmax.
// ===========================================================================
#define QLB 18432
#define KVB 36864
#define KVBUF 36864
#define FLASH_SMEM 110592
#define FSHIFT 8.0f

__global__ void __launch_bounds__(256, 2) flash_tc_kernel(float* __restrict__ Out)
{
    extern __shared__ uint32_t sm[];
    const uint32_t sb = smem_u32(sm);

    const int tid = threadIdx.x;
    const int wid = tid >> 5;
    const int lane = tid & 31;
    const int g = lane >> 2;
    const int t = lane & 3;
    const int qt = blockIdx.x;
    const int h  = blockIdx.y;
    const int b  = blockIdx.z;

    const size_t bh = ((size_t)b * HH + h) * TT * HD;
    const __nv_bfloat16* Qhi = g_qhi + bh + (size_t)qt * 128 * HD;
    const __nv_bfloat16* Qlo = g_qlo + bh + (size_t)qt * 128 * HD;
    const __nv_bfloat16* Khi = g_khi + bh;
    const __nv_bfloat16* Klo = g_klo + bh;
    const __nv_bfloat16* Vhi = g_vhi + bh;
    const __nv_bfloat16* Vlo = g_vlo + bh;

#pragma unroll
    for (int it = 0; it < 8; it++) {
        int lin = tid + it * 256;
        int arr = it >> 2;
        int rem = lin & 1023;
        int row = rem >> 3;
        int seg = rem & 7;
        const __nv_bfloat16* src = (arr == 0 ? Qhi : Qlo) + row * HD + seg * 8;
        cp_async16(sb + arr * QLB + row * 144 + seg * 16, src);
    }

    auto issue_kv = [&](int jt, int s) {
#pragma unroll
        for (int it = 0; it < 8; it++) {
            int lin = tid + it * 256;
            int arr = it >> 1;
            int rem = lin & 511;
            int row = rem >> 3;
            int seg = rem & 7;
            const __nv_bfloat16* base =
                (arr == 0) ? Khi : (arr == 1) ? Klo : (arr == 2) ? Vhi : Vlo;
            cp_async16(sb + KVB + s * KVBUF + arr * 9216 + row * 144 + seg * 16,
                       base + (size_t)(jt * 64 + row) * HD + seg * 8);
        }
        asm volatile("cp.async.commit_group;\n" ::: "memory");
    };

    issue_kv(0, 0);

    float o[8][4];
#pragma unroll
    for (int j = 0; j < 8; j++)
#pragma unroll
        for (int i = 0; i < 4; i++) o[j][i] = 0.f;
    float li0 = 0.f, li1 = 0.f;

    const int mq = wid * 16;
    const uint32_t qa_base = sb + (mq + (lane & 15)) * 144 + ((lane >> 4) << 4);
    const uint32_t ka_off = (((lane >> 4) << 3) + (lane & 7)) * 144
                          + (((lane >> 3) & 1) << 4);
    const uint32_t va_off = ((((lane >> 3) & 1) << 3) + (lane & 7)) * 144
                          + ((lane >> 4) << 4);

    for (int jt = 0; jt < TT / 64; jt++) {
        asm volatile("cp.async.wait_group 0;\n" ::: "memory");
        __syncthreads();

        if (jt + 1 < TT / 64) issue_kv(jt + 1, (jt + 1) & 1);

        const uint32_t kbuf = sb + KVB + (jt & 1) * KVBUF;

        float sc[8][4];
#pragma unroll
        for (int j = 0; j < 8; j++)
#pragma unroll
            for (int i = 0; i < 4; i++) sc[j][i] = 0.f;

#pragma unroll
        for (int kb = 0; kb < 4; kb++) {
            uint32_t aH[4], aL[4];
            ldsm4(aH, qa_base + kb * 32);
            ldsm4(aL, qa_base + kb * 32 + QLB);
#pragma unroll
            for (int jp = 0; jp < 4; jp++) {
                uint32_t kaddr = kbuf + ka_off + jp * 16 * 144 + kb * 32;
                uint32_t bH[4], bL[4];
                ldsm4(bH, kaddr);
                ldsm4(bL, kaddr + 9216);
                mma_bf16(sc[2 * jp],     aH, &bH[0]);
                mma_bf16(sc[2 * jp],     aH, &bL[0]);
                mma_bf16(sc[2 * jp],     aL, &bH[0]);
                mma_bf16(sc[2 * jp + 1], aH, &bH[2]);
                mma_bf16(sc[2 * jp + 1], aH, &bL[2]);
                mma_bf16(sc[2 * jp + 1], aL, &bH[2]);
            }
        }

        float rs0 = 0.f, rs1 = 0.f;
#pragma unroll
        for (int j = 0; j < 8; j++) {
            sc[j][0] = __expf(sc[j][0] - FSHIFT);
            sc[j][1] = __expf(sc[j][1] - FSHIFT);
            sc[j][2] = __expf(sc[j][2] - FSHIFT);
            sc[j][3] = __expf(sc[j][3] - FSHIFT);
            rs0 += sc[j][0] + sc[j][1];
            rs1 += sc[j][2] + sc[j][3];
        }
        li0 += rs0;
        li1 += rs1;

#pragma unroll
        for (int kb = 0; kb < 4; kb++) {
            uint32_t aH[4], aL[4];
            split2(sc[2 * kb][0],     sc[2 * kb][1],     aH[0], aL[0]);
            split2(sc[2 * kb][2],     sc[2 * kb][3],     aH[1], aL[1]);
            split2(sc[2 * kb + 1][0], sc[2 * kb + 1][1], aH[2], aL[2]);
            split2(sc[2 * kb + 1][2], sc[2 * kb + 1][3], aH[3], aL[3]);
#pragma unroll
            for (int jp = 0; jp < 4; jp++) {
                uint32_t vaddr = kbuf + 18432 + va_off + kb * 16 * 144 + jp * 32;
                uint32_t bH[4], bL[4];
                ldsm4t(bH, vaddr);
                ldsm4t(bL, vaddr + 9216);
                mma_bf16(o[2 * jp],     aH, &bH[0]);
                mma_bf16(o[2 * jp],     aH, &bL[0]);
                mma_bf16(o[2 * jp],     aL, &bH[0]);
                mma_bf16(o[2 * jp + 1], aH, &bH[2]);
                mma_bf16(o[2 * jp + 1], aH, &bL[2]);
                mma_bf16(o[2 * jp + 1], aL, &bH[2]);
            }
        }
    }

    li0 += __shfl_xor_sync(0xffffffffu, li0, 1);
    li0 += __shfl_xor_sync(0xffffffffu, li0, 2);
    li1 += __shfl_xor_sync(0xffffffffu, li1, 1);
    li1 += __shfl_xor_sync(0xffffffffu, li1, 2);
    float inv0 = 1.f / li0, inv1 = 1.f / li1;
    int row0 = qt * 128 + mq + g;
#pragma unroll
    for (int j = 0; j < 8; j++) {
        int col = h * HD + j * 8 + 2 * t;
        float2 r0 = make_float2(__uint_as_float(f2tf32(o[j][0] * inv0)),
                                __uint_as_float(f2tf32(o[j][1] * inv0)));
        float2 r1 = make_float2(__uint_as_float(f2tf32(o[j][2] * inv1)),
                                __uint_as_float(f2tf32(o[j][3] * inv1)));
        *(float2*)(Out + ((size_t)b * TT + row0) * DD + col) = r0;
        *(float2*)(Out + ((size_t)b * TT + row0 + 8) * DD + col) = r1;
    }
}

// ---------------------------------------------------------------------------
extern "C" void kernel_launch(void* const* d_in, const int* in_sizes, int n_in,
                              void* d_out, int out_size)
{
    const float* q  = (const float*)d_in[0];
    const float* k  = (const float*)d_in[1];
    const float* v  = (const float*)d_in[2];
    const float* Wq = (const float*)d_in[3];
    const float* bq = (const float*)d_in[4];
    const float* Wk = (const float*)d_in[5];
    const float* bk = (const float*)d_in[6];
    const float* Wv = (const float*)d_in[7];
    const float* bv = (const float*)d_in[8];
    const float* Wo = (const float*)d_in[9];
    const float* bo = (const float*)d_in[10];
    float* out = (float*)d_out;

    float* attn;
    cudaGetSymbolAddress((void**)&attn, g_attn);

    cudaFuncSetAttribute(flash_tc_kernel,
                         cudaFuncAttributeMaxDynamicSharedMemorySize, FLASH_SMEM);
    cudaFuncSetAttribute(gemm_qkv_kernel,
                         cudaFuncAttributeMaxDynamicSharedMemorySize, GEMM_SMEM);
    cudaFuncSetAttribute(gemm_o_kernel,
                         cudaFuncAttributeMaxDynamicSharedMemorySize, GEMM_SMEM);

    dim3 cgrid((MM * DD) / (256 * 4), 7);
    cvt_all_kernel<<<cgrid, 256>>>(q, k, v, Wq, Wk, Wv, Wo);

    dim3 qkvgrid(DD / 128, MM / 128, 3);   // (8, 32, 3)
    gemm_qkv_kernel<<<qkvgrid, 256, GEMM_SMEM>>>(bq, bk, bv);

    dim3 fgrid(TT / 128, HH, BB);          // (16, 16, 2)
    flash_tc_kernel<<<fgrid, 256, FLASH_SMEM>>>(attn);

    dim3 ogrid(DD / 128, MM / 128);        // (8, 32)
    gemm_o_kernel<<<ogrid, 256, GEMM_SMEM>>>(bo, out);
}